// round 15
// baseline (speedup 1.0000x reference)
#include <cuda_runtime.h>
#include <cstdint>
#include <cstddef>

// Problem dims
constexpr int kB  = 16;    // batch
constexpr int kN  = 512;   // num inputs
constexpr int kU  = 512;   // num units
constexpr int kT  = 1024;  // time = H*H
constexpr int kH  = 32;    // heads
constexpr int kCB = 512;   // C*B
constexpr float kNEG  = -4294967296.0f;  // float32(-2^32+1)
constexpr float kKEEP = 0.9f;
constexpr float kRKEEP = 1.0f / 0.9f;
constexpr float kUnif  = 1.0f / (0.9f * 512.0f);  // uniform prob for all-masked col

constexpr int    kNN     = kN * kN;                 // 262144
constexpr size_t kPSZ    = (size_t)kCB * kNN;       // 134217728
constexpr int    kOUTSZ  = kH * kN * kB * kH;       // 8388608
constexpr int    kATTSZ  = kCB * kN;                // 262144

// Scratch (__device__ globals per allocation-free contract)
// NOTE: g_P and g_d are stored TRANSPOSED: linear index = m*kN + n (per cb).
// Threefry indices always use the LOGICAL index ((cb*N + n)*N + m).
__device__ float g_Q[(size_t)kCB * kN * kH];
__device__ float g_K[(size_t)kCB * kN * kH];
__device__ float g_V[(size_t)kCB * kN * kH];
__device__ float g_P[kPSZ];          // raw (masked) scores, [cb][m][n]
__device__ float g_d[kNN];           // mx + ln(0.9 * sum_exp), [m][n]
__device__ int   g_skip[kB * kN];    // 0 normal / 1 zero-col / 2 uniform-col

// ---------------- threefry2x32 (exact JAX PRNG, partitionable layout) --------------
__device__ __forceinline__ void tf_round(uint32_t& a, uint32_t& b, int r) {
    a += b;
    b = __funnelshift_l(b, b, r);
    b ^= a;
}
__device__ __forceinline__ void threefry(uint32_t k0, uint32_t k1,
                                         uint32_t& x0, uint32_t& x1) {
    uint32_t k2 = k0 ^ k1 ^ 0x1BD11BDAu;
    x0 += k0; x1 += k1;
    tf_round(x0,x1,13); tf_round(x0,x1,15); tf_round(x0,x1,26); tf_round(x0,x1,6);
    x0 += k1; x1 += k2 + 1u;
    tf_round(x0,x1,17); tf_round(x0,x1,29); tf_round(x0,x1,16); tf_round(x0,x1,24);
    x0 += k2; x1 += k0 + 2u;
    tf_round(x0,x1,13); tf_round(x0,x1,15); tf_round(x0,x1,26); tf_round(x0,x1,6);
    x0 += k0; x1 += k1 + 3u;
    tf_round(x0,x1,17); tf_round(x0,x1,29); tf_round(x0,x1,16); tf_round(x0,x1,24);
    x0 += k1; x1 += k2 + 4u;
    tf_round(x0,x1,13); tf_round(x0,x1,15); tf_round(x0,x1,26); tf_round(x0,x1,6);
    x0 += k2; x1 += k0 + 5u;
}
__device__ __forceinline__ uint32_t rng_bits(uint32_t k1, uint32_t idx) {
    uint32_t x0 = 0u, x1 = idx;
    threefry(0u, k1, x0, x1);
    return x0 ^ x1;
}
__device__ __forceinline__ bool keep_bit(uint32_t bits) {
    float u = __uint_as_float((bits >> 9) | 0x3f800000u) - 1.0f;
    return u < kKEEP;
}

// ---------------- tf32 helpers ----------------
__device__ __forceinline__ uint32_t f2tf32(float v) {
    uint32_t r;
    asm("cvt.rna.tf32.f32 %0, %1;" : "=r"(r) : "f"(v));
    return r;
}
// On-the-fly 2-term split at fragment-load time: bit-identical to the old
// stored-plane scheme (hi = rna-tf32(v); lo = rna-tf32(v - hi)).
__device__ __forceinline__ void split2(float v, uint32_t& hi, uint32_t& lo) {
    hi = f2tf32(v);
    lo = f2tf32(v - __uint_as_float(hi));
}
__device__ __forceinline__ void mma_tf32(float& d0, float& d1, float& d2, float& d3,
                                         uint32_t a0, uint32_t a1, uint32_t a2, uint32_t a3,
                                         uint32_t b0, uint32_t b1) {
    asm volatile(
        "mma.sync.aligned.m16n8k8.row.col.f32.tf32.tf32.f32 "
        "{%0,%1,%2,%3}, {%4,%5,%6,%7}, {%8,%9}, {%0,%1,%2,%3};"
        : "+f"(d0), "+f"(d1), "+f"(d2), "+f"(d3)
        : "r"(a0), "r"(a1), "r"(a2), "r"(a3), "r"(b0), "r"(b1));
}

// ---------------- K0: per-(b,m) skip codes from padding mask ----------------------
__global__ void __launch_bounds__(256) skip_kernel(const int* __restrict__ pm) {
    int idx = blockIdx.x * blockDim.x + threadIdx.x;   // 0..kB*kN-1
    int b = idx >> 9, m = idx & 511;
    bool allm = true;
#pragma unroll
    for (int bb = 0; bb < kB; bb++) allm = allm && (pm[bb * kN + m] == 0);
    int code = 0;
    if (allm) code = 2;                                // uniform softmax column
    else if (pm[b * kN + m] == 0) code = 1;            // exactly-zero column
    g_skip[idx] = code;
}

// ---------------- K1: projections via tf32 mma, raw-f32 tiles, split at load ------
__global__ void __launch_bounds__(256) proj_kernel(const float* __restrict__ x,
                                                   const float* __restrict__ Qp,
                                                   const float* __restrict__ Kp,
                                                   const float* __restrict__ Vp) {
    int z = blockIdx.z;                 // mat*16 + b
    int mat = z >> 4, b = z & 15;
    const float* W  = (mat == 0) ? Qp : ((mat == 1) ? Kp : Vp);
    float* Out      = (mat == 0) ? g_Q : ((mat == 1) ? g_K : g_V);
    const float* X  = x + (size_t)b * kU * kT;

    int n0 = blockIdx.y * 128;          // output n (m-dim)
    int t0 = blockIdx.x * 128;          // output t (n-dim)

    __shared__ float Ws[128][20];       // raw f32 [n][k]
    __shared__ float Xs[16][136];       // raw f32 [k][t]

    int tid = threadIdx.x;              // 256
    int w   = tid >> 5;
    int lane= tid & 31;
    int g   = lane >> 2;
    int tig = lane & 3;

    int wm = (w & 3) * 32;
    int wn = (w >> 2) * 64;

    float acc[2][8][4] = {};

    for (int k0 = 0; k0 < kU; k0 += 16) {
        __syncthreads();
#pragma unroll
        for (int i = 0; i < 2; i++) {   // W tile: 128 n x 16 k (float4 STS)
            int idx = tid + i * 256;
            int n = idx >> 2, c4 = idx & 3;
            *(float4*)&Ws[n][c4 * 4] =
                *(const float4*)&W[(size_t)(n0 + n) * kU + k0 + c4 * 4];
        }
#pragma unroll
        for (int i = 0; i < 2; i++) {   // X tile: 16 k x 128 t
            int idx = tid + i * 256;
            int k = idx >> 5, c4 = idx & 31;
            *(float4*)&Xs[k][c4 * 4] =
                *(const float4*)&X[(size_t)(k0 + k) * kT + t0 + c4 * 4];
        }
        __syncthreads();

#pragma unroll
        for (int kk = 0; kk < 16; kk += 8) {
            uint32_t ah[2][4], al[2][4];
#pragma unroll
            for (int mt = 0; mt < 2; mt++) {
                int r = wm + mt * 16 + g;
                split2(Ws[r    ][kk + tig    ], ah[mt][0], al[mt][0]);
                split2(Ws[r + 8][kk + tig    ], ah[mt][1], al[mt][1]);
                split2(Ws[r    ][kk + tig + 4], ah[mt][2], al[mt][2]);
                split2(Ws[r + 8][kk + tig + 4], ah[mt][3], al[mt][3]);
            }
#pragma unroll
            for (int j = 0; j < 8; j++) {
                int col = wn + j * 8 + g;
                uint32_t bh0, bl0, bh1, bl1;
                split2(Xs[kk + tig    ][col], bh0, bl0);
                split2(Xs[kk + tig + 4][col], bh1, bl1);
#pragma unroll
                for (int mt = 0; mt < 2; mt++) {
                    mma_tf32(acc[mt][j][0], acc[mt][j][1], acc[mt][j][2], acc[mt][j][3],
                             ah[mt][0], ah[mt][1], ah[mt][2], ah[mt][3], bh0, bh1);
                    mma_tf32(acc[mt][j][0], acc[mt][j][1], acc[mt][j][2], acc[mt][j][3],
                             ah[mt][0], ah[mt][1], ah[mt][2], ah[mt][3], bl0, bl1);
                    mma_tf32(acc[mt][j][0], acc[mt][j][1], acc[mt][j][2], acc[mt][j][3],
                             al[mt][0], al[mt][1], al[mt][2], al[mt][3], bh0, bh1);
                }
            }
        }
    }

#pragma unroll
    for (int mt = 0; mt < 2; mt++) {
        int r0 = n0 + wm + mt * 16 + g;
#pragma unroll
        for (int j = 0; j < 8; j++) {
            int t = t0 + wn + j * 8 + 2 * tig;
            int c = t >> 5, h = t & 31;
            float* base = &Out[((size_t)(c * 16 + b) * kN) * kH + h];
            *(float2*)&base[(size_t)r0 * kH]       = make_float2(acc[mt][j][0], acc[mt][j][1]);
            *(float2*)&base[(size_t)(r0 + 8) * kH] = make_float2(acc[mt][j][2], acc[mt][j][3]);
        }
    }
}

// ---------------- K2: scores via tf32 mma, raw-f32 tiles, split at load -----------
__global__ void __launch_bounds__(256) scores_kernel(const int* __restrict__ pm) {
    int cb = blockIdx.z;
    int bb = cb & 15;
    int m0 = blockIdx.x * 64, n0 = blockIdx.y * 64;
    const float* Q = g_Q + (size_t)cb * kN * kH;
    const float* K = g_K + (size_t)cb * kN * kH;

    __shared__ float Qs[64][36];        // raw f32 [n][h]
    __shared__ float Ks[64][36];        // raw f32 [m][h]
    __shared__ int pmsk[64];

    int tid = threadIdx.x;              // 256
    if (tid < 64) pmsk[tid] = pm[bb * kN + m0 + tid];

#pragma unroll
    for (int i = 0; i < 2; i++) {       // fill both tiles, float4 STS
        int idx = tid + i * 256;
        int r = idx >> 3, c4 = idx & 7;
        *(float4*)&Qs[r][c4 * 4] = *(const float4*)&Q[(size_t)(n0 + r) * kH + c4 * 4];
        *(float4*)&Ks[r][c4 * 4] = *(const float4*)&K[(size_t)(m0 + r) * kH + c4 * 4];
    }
    __syncthreads();

    int w = tid >> 5, lane = tid & 31;
    int g = lane >> 2, tig = lane & 3;
    int wm = (w & 1) * 32;              // n offset within 64
    int wnn = (w >> 1) * 16;            // m offset within 64

    float acc[2][2][4] = {};

#pragma unroll
    for (int kk = 0; kk < 32; kk += 8) {
        uint32_t ah[2][4], al[2][4];
#pragma unroll
        for (int mt = 0; mt < 2; mt++) {
            int r = wm + mt * 16 + g;
            split2(Qs[r    ][kk + tig    ], ah[mt][0], al[mt][0]);
            split2(Qs[r + 8][kk + tig    ], ah[mt][1], al[mt][1]);
            split2(Qs[r    ][kk + tig + 4], ah[mt][2], al[mt][2]);
            split2(Qs[r + 8][kk + tig + 4], ah[mt][3], al[mt][3]);
        }
#pragma unroll
        for (int j = 0; j < 2; j++) {
            int col = wnn + j * 8 + g;
            uint32_t bh0, bl0, bh1, bl1;
            split2(Ks[col][kk + tig    ], bh0, bl0);
            split2(Ks[col][kk + tig + 4], bh1, bl1);
#pragma unroll
            for (int mt = 0; mt < 2; mt++) {
                mma_tf32(acc[mt][j][0], acc[mt][j][1], acc[mt][j][2], acc[mt][j][3],
                         ah[mt][0], ah[mt][1], ah[mt][2], ah[mt][3], bh0, bh1);
                mma_tf32(acc[mt][j][0], acc[mt][j][1], acc[mt][j][2], acc[mt][j][3],
                         ah[mt][0], ah[mt][1], ah[mt][2], ah[mt][3], bl0, bl1);
                mma_tf32(acc[mt][j][0], acc[mt][j][1], acc[mt][j][2], acc[mt][j][3],
                         al[mt][0], al[mt][1], al[mt][2], al[mt][3], bh0, bh1);
            }
        }
    }

    // epilogue with key mask, TRANSPOSED store g_P[cb][m][n]
    float* Pt = g_P + (size_t)cb * kNN;
#pragma unroll
    for (int mt = 0; mt < 2; mt++) {
        int n = n0 + wm + mt * 16 + g;
#pragma unroll
        for (int j = 0; j < 2; j++) {
            int mc = wnn + j * 8 + 2 * tig;
            int m = m0 + mc;
            float c0 = (pmsk[mc]     == 0) ? kNEG : acc[mt][j][0];
            float c1 = (pmsk[mc + 1] == 0) ? kNEG : acc[mt][j][1];
            float c2 = (pmsk[mc]     == 0) ? kNEG : acc[mt][j][2];
            float c3 = (pmsk[mc + 1] == 0) ? kNEG : acc[mt][j][3];
            Pt[(size_t)m * kN + n]           = c0;
            Pt[(size_t)(m + 1) * kN + n]     = c1;
            Pt[(size_t)m * kN + n + 8]       = c2;
            Pt[(size_t)(m + 1) * kN + n + 8] = c3;
        }
    }
}

// ---------------- K3: online max & sumexp over axis 0; d = mx + ln(0.9 s) ---------
__global__ void __launch_bounds__(256) maxsum_kernel() {
    int idx = blockIdx.x * blockDim.x + threadIdx.x;  // 0..N*N-1 (= m*kN + n)
    const float* p = g_P + idx;
    float mx = __int_as_float(0xff800000);            // -inf
    float s = 0.0f;
    for (int cb = 0; cb < kCB; cb += 8) {
        float v[8];
#pragma unroll
        for (int u = 0; u < 8; u++) v[u] = p[(size_t)(cb + u) * kNN];
#pragma unroll
        for (int u = 0; u < 8; u++) {
            float vv = v[u];
            if (vv > mx) { s = s * __expf(mx - vv) + 1.0f; mx = vv; }
            else         { s += __expf(vv - mx); }
        }
    }
    g_d[idx] = mx + __logf(kKEEP * s);
}

// ---------------- K4: ctx = dropout(softmax) @ Vh, tf32 mma -----------------------
// P single tf32 plane; V raw-f32 transposed tile, 2-term split at frag load.
__global__ void __launch_bounds__(256) ctx_kernel(float* __restrict__ out) {
    int cb = blockIdx.y;
    int n0 = blockIdx.x * 64;
    int bb = cb & 15;
    const float* Pt = g_P + (size_t)cb * kNN;   // [m][n]
    const float* V = g_V + (size_t)cb * kN * kH;

    __shared__ float Ph[32][72];                // [m][n]  (m-tile 32), tf32 values
    __shared__ float Vt[32][36];                // raw f32 [h][m]
    __shared__ int skipw[kN];

    int tid = threadIdx.x;                      // 256
    for (int i = tid; i < kN; i += 256) skipw[i] = g_skip[bb * kN + i];

    int w = tid >> 5, l = tid & 31;
    int g = l >> 2, tig = l & 3;
    int wh = (w & 1) * 16;                      // h-offset of warp tile (A rows)
    int wn = (w >> 1) * 16;                     // n-offset of warp tile (B cols)

    float acc[2][4] = {};                       // [j][frag]: D[h][n], 16h x 16n/warp

    __syncthreads();

    for (int m0 = 0; m0 < kN; m0 += 32) {
        // ---- V tile transpose: [m][h] -> [h][m], raw f32 ----
        {
            int k = tid >> 3, h4 = tid & 7;
            float4 v = *(const float4*)&V[(size_t)(m0 + k) * kH + h4 * 4];
            Vt[h4 * 4 + 0][k] = v.x;
            Vt[h4 * 4 + 1][k] = v.y;
            Vt[h4 * 4 + 2][k] = v.z;
            Vt[h4 * 4 + 3][k] = v.w;
        }
        // ---- threefry fill: warp-uniform m, coalesced gmem reads ----
#pragma unroll 2
        for (int j = 0; j < 4; j++) {
            int ml = w * 4 + j;
            int m = m0 + ml;
            int sk = skipw[m];
            if (sk == 1) {
                Ph[ml][l] = 0.0f; Ph[ml][l + 32] = 0.0f;
            } else {
                const float* prow = &Pt[(size_t)m * kN + n0];
                const float* drow = &g_d[m * kN + n0];
#pragma unroll
                for (int rr = 0; rr < 2; rr++) {
                    int nl = l + rr * 32;
                    float pr = (sk == 2) ? kUnif
                                         : __expf(prow[nl] - drow[nl]);
                    uint32_t gi = (uint32_t)(((size_t)cb * kN + n0 + nl) * kN + m);
                    uint32_t bits = rng_bits(1u, gi);   // key(1), LOGICAL index
                    float val = keep_bit(bits) ? pr : 0.0f;
                    Ph[ml][nl] = __uint_as_float(f2tf32(val));
                }
            }
        }
        __syncthreads();
        // ---- MMA: A = Vt (16 h rows, hi+lo at load), B = P (tf32), k = 32 m ----
#pragma unroll
        for (int kk = 0; kk < 32; kk += 8) {
            int r = wh + g;
            uint32_t ah[4], al[4];
            split2(Vt[r    ][kk + tig    ], ah[0], al[0]);
            split2(Vt[r + 8][kk + tig    ], ah[1], al[1]);
            split2(Vt[r    ][kk + tig + 4], ah[2], al[2]);
            split2(Vt[r + 8][kk + tig + 4], ah[3], al[3]);
#pragma unroll
            for (int j = 0; j < 2; j++) {
                int col = wn + j * 8 + g;
                uint32_t bh0 = __float_as_uint(Ph[kk + tig    ][col]);
                uint32_t bh1 = __float_as_uint(Ph[kk + tig + 4][col]);
                mma_tf32(acc[j][0], acc[j][1], acc[j][2], acc[j][3],
                         ah[0], ah[1], ah[2], ah[3], bh0, bh1);
                mma_tf32(acc[j][0], acc[j][1], acc[j][2], acc[j][3],
                         al[0], al[1], al[2], al[3], bh0, bh1);
            }
        }
        __syncthreads();
    }

    // epilogue: D[h][n] -> out[jj, n, ii*32+h] with cb = ii*32+jj; dropout key(2)
    int jpart = (cb & 31) * (kN * kB * kH) + (cb >> 5) * kH;
#pragma unroll
    for (int j = 0; j < 2; j++) {
        int nc = n0 + wn + j * 8 + 2 * tig;
#pragma unroll
        for (int rr = 0; rr < 2; rr++) {
            int h = wh + g + rr * 8;
            int oidx0 = jpart + nc * (kB * kH) + h;
            int oidx1 = oidx0 + kB * kH;        // n+1
            float v0 = acc[j][rr * 2 + 0];
            float v1 = acc[j][rr * 2 + 1];
            uint32_t b0 = rng_bits(2u, (uint32_t)oidx0);
            uint32_t b1 = rng_bits(2u, (uint32_t)oidx1);
            out[oidx0] = keep_bit(b0) ? v0 * kRKEEP : 0.0f;
            out[oidx1] = keep_bit(b1) ? v1 * kRKEEP : 0.0f;
        }
    }
}

// ---------------- K5: attention = dropout(probs)[:, N-1, :] recomputed ------------
__global__ void __launch_bounds__(256) attn_kernel(float* __restrict__ out) {
    int idx = blockIdx.x * blockDim.x + threadIdx.x;  // 0..kATTSZ-1
    int cb = idx >> 9, m = idx & 511;
    int bb = cb & 15;
    int sk = g_skip[bb * kN + m];
    size_t ti = (size_t)cb * kNN + (size_t)m * kN + (kN - 1);
    float pr = (sk == 2) ? kUnif : __expf(g_P[ti] - g_d[m * kN + (kN - 1)]);
    uint32_t gi = (uint32_t)(((size_t)cb * kN + (kN - 1)) * kN + m);  // logical
    uint32_t bits = rng_bits(1u, gi);
    out[kOUTSZ + idx] = keep_bit(bits) ? pr : 0.0f;
}

extern "C" void kernel_launch(void* const* d_in, const int* in_sizes, int n_in,
                              void* d_out, int out_size) {
    const float* x  = (const float*)d_in[0];
    const float* Qp = (const float*)d_in[1];
    const float* Kp = (const float*)d_in[2];
    const float* Vp = (const float*)d_in[3];
    const int*   pm = (const int*)d_in[4];
    float* out = (float*)d_out;

    skip_kernel  <<<(kB * kN) / 256, 256>>>(pm);
    proj_kernel  <<<dim3(kT / 128, kN / 128, 48), 256>>>(x, Qp, Kp, Vp);
    scores_kernel<<<dim3(kN / 64, kN / 64, kCB), 256>>>(pm);
    maxsum_kernel<<<kNN / 256, 256>>>();
    ctx_kernel   <<<dim3(kN / 64, kCB), 256>>>(out);
    if (out_size >= kOUTSZ + kATTSZ) {
        attn_kernel<<<kATTSZ / 256, 256>>>(out);
    }
}

// round 16
// speedup vs baseline: 1.4042x; 1.4042x over previous
#include <cuda_runtime.h>
#include <cstdint>
#include <cstddef>

// Problem dims
constexpr int kB  = 16;    // batch
constexpr int kN  = 512;   // num inputs
constexpr int kU  = 512;   // num units
constexpr int kT  = 1024;  // time = H*H
constexpr int kH  = 32;    // heads
constexpr int kCB = 512;   // C*B
constexpr float kNEG  = -4294967296.0f;  // float32(-2^32+1)
constexpr float kKEEP = 0.9f;
constexpr float kRKEEP = 1.0f / 0.9f;
constexpr float kUnif  = 1.0f / (0.9f * 512.0f);  // uniform prob for all-masked col

constexpr int    kNN     = kN * kN;                 // 262144
constexpr size_t kPSZ    = (size_t)kCB * kNN;       // 134217728
constexpr int    kOUTSZ  = kH * kN * kB * kH;       // 8388608
constexpr int    kATTSZ  = kCB * kN;                // 262144

// Scratch (__device__ globals per allocation-free contract)
// NOTE: g_P and g_d are stored TRANSPOSED: linear index = m*kN + n (per cb).
// Threefry indices always use the LOGICAL index ((cb*N + n)*N + m).
__device__ float g_Q[(size_t)kCB * kN * kH];
__device__ float g_K[(size_t)kCB * kN * kH];
__device__ float g_V[(size_t)kCB * kN * kH];
__device__ float g_P[kPSZ];          // raw (masked) scores, [cb][m][n]
__device__ float g_d[kNN];           // mx + ln(0.9 * sum_exp), [m][n]
__device__ int   g_skip[kB * kN];    // 0 normal / 1 zero-col / 2 uniform-col

// ---------------- threefry2x32 (exact JAX PRNG, partitionable layout) --------------
__device__ __forceinline__ void tf_round(uint32_t& a, uint32_t& b, int r) {
    a += b;
    b = __funnelshift_l(b, b, r);
    b ^= a;
}
__device__ __forceinline__ void threefry(uint32_t k0, uint32_t k1,
                                         uint32_t& x0, uint32_t& x1) {
    uint32_t k2 = k0 ^ k1 ^ 0x1BD11BDAu;
    x0 += k0; x1 += k1;
    tf_round(x0,x1,13); tf_round(x0,x1,15); tf_round(x0,x1,26); tf_round(x0,x1,6);
    x0 += k1; x1 += k2 + 1u;
    tf_round(x0,x1,17); tf_round(x0,x1,29); tf_round(x0,x1,16); tf_round(x0,x1,24);
    x0 += k2; x1 += k0 + 2u;
    tf_round(x0,x1,13); tf_round(x0,x1,15); tf_round(x0,x1,26); tf_round(x0,x1,6);
    x0 += k0; x1 += k1 + 3u;
    tf_round(x0,x1,17); tf_round(x0,x1,29); tf_round(x0,x1,16); tf_round(x0,x1,24);
    x0 += k1; x1 += k2 + 4u;
    tf_round(x0,x1,13); tf_round(x0,x1,15); tf_round(x0,x1,26); tf_round(x0,x1,6);
    x0 += k2; x1 += k0 + 5u;
}
__device__ __forceinline__ uint32_t rng_bits(uint32_t k1, uint32_t idx) {
    uint32_t x0 = 0u, x1 = idx;
    threefry(0u, k1, x0, x1);
    return x0 ^ x1;
}
__device__ __forceinline__ bool keep_bit(uint32_t bits) {
    float u = __uint_as_float((bits >> 9) | 0x3f800000u) - 1.0f;
    return u < kKEEP;
}

// ---------------- tf32 helpers ----------------
__device__ __forceinline__ uint32_t f2tf32(float v) {
    uint32_t r;
    asm("cvt.rna.tf32.f32 %0, %1;" : "=r"(r) : "f"(v));
    return r;
}
__device__ __forceinline__ void split_tf32(float v, float& hi, float& lo) {
    uint32_t h = f2tf32(v);
    hi = __uint_as_float(h);
    lo = v - hi;
}
__device__ __forceinline__ void mma_tf32(float& d0, float& d1, float& d2, float& d3,
                                         uint32_t a0, uint32_t a1, uint32_t a2, uint32_t a3,
                                         uint32_t b0, uint32_t b1) {
    asm volatile(
        "mma.sync.aligned.m16n8k8.row.col.f32.tf32.tf32.f32 "
        "{%0,%1,%2,%3}, {%4,%5,%6,%7}, {%8,%9}, {%0,%1,%2,%3};"
        : "+f"(d0), "+f"(d1), "+f"(d2), "+f"(d3)
        : "r"(a0), "r"(a1), "r"(a2), "r"(a3), "r"(b0), "r"(b1));
}

// ---------------- K0: per-(b,m) skip codes from padding mask ----------------------
__global__ void __launch_bounds__(256) skip_kernel(const int* __restrict__ pm) {
    int idx = blockIdx.x * blockDim.x + threadIdx.x;   // 0..kB*kN-1
    int b = idx >> 9, m = idx & 511;
    bool allm = true;
#pragma unroll
    for (int bb = 0; bb < kB; bb++) allm = allm && (pm[bb * kN + m] == 0);
    int code = 0;
    if (allm) code = 2;                                // uniform softmax column
    else if (pm[b * kN + m] == 0) code = 1;            // exactly-zero column
    g_skip[idx] = code;
}

// ---------------- K1: projections via tf32 mma (2-term split, 3 MMAs) -------------
__global__ void __launch_bounds__(256) proj_kernel(const float* __restrict__ x,
                                                   const float* __restrict__ Qp,
                                                   const float* __restrict__ Kp,
                                                   const float* __restrict__ Vp) {
    int z = blockIdx.z;                 // mat*16 + b
    int mat = z >> 4, b = z & 15;
    const float* W  = (mat == 0) ? Qp : ((mat == 1) ? Kp : Vp);
    float* Out      = (mat == 0) ? g_Q : ((mat == 1) ? g_K : g_V);
    const float* X  = x + (size_t)b * kU * kT;

    int n0 = blockIdx.y * 128;          // output n (m-dim)
    int t0 = blockIdx.x * 128;          // output t (n-dim)

    __shared__ float Wh[128][20];
    __shared__ float Wl[128][20];
    __shared__ float Xh[16][136];
    __shared__ float Xl[16][136];

    int tid = threadIdx.x;              // 256
    int w   = tid >> 5;
    int lane= tid & 31;
    int g   = lane >> 2;
    int tig = lane & 3;

    int wm = (w & 3) * 32;
    int wn = (w >> 2) * 64;

    float acc[2][8][4] = {};

    for (int k0 = 0; k0 < kU; k0 += 16) {
        __syncthreads();
#pragma unroll
        for (int i = 0; i < 2; i++) {
            int idx = tid + i * 256;
            int n = idx >> 2, c4 = idx & 3;
            float4 v = *(const float4*)&W[(size_t)(n0 + n) * kU + k0 + c4 * 4];
            float h0,l0,h1,l1,h2,l2,h3,l3;
            split_tf32(v.x, h0, l0); split_tf32(v.y, h1, l1);
            split_tf32(v.z, h2, l2); split_tf32(v.w, h3, l3);
            Wh[n][c4*4+0] = h0; Wh[n][c4*4+1] = h1; Wh[n][c4*4+2] = h2; Wh[n][c4*4+3] = h3;
            Wl[n][c4*4+0] = l0; Wl[n][c4*4+1] = l1; Wl[n][c4*4+2] = l2; Wl[n][c4*4+3] = l3;
        }
#pragma unroll
        for (int i = 0; i < 2; i++) {
            int idx = tid + i * 256;
            int k = idx >> 5, c4 = idx & 31;
            float4 v = *(const float4*)&X[(size_t)(k0 + k) * kT + t0 + c4 * 4];
            float h0,l0,h1,l1,h2,l2,h3,l3;
            split_tf32(v.x, h0, l0); split_tf32(v.y, h1, l1);
            split_tf32(v.z, h2, l2); split_tf32(v.w, h3, l3);
            Xh[k][c4*4+0] = h0; Xh[k][c4*4+1] = h1; Xh[k][c4*4+2] = h2; Xh[k][c4*4+3] = h3;
            Xl[k][c4*4+0] = l0; Xl[k][c4*4+1] = l1; Xl[k][c4*4+2] = l2; Xl[k][c4*4+3] = l3;
        }
        __syncthreads();

#pragma unroll
        for (int kk = 0; kk < 16; kk += 8) {
            uint32_t ah[2][4], al[2][4];
#pragma unroll
            for (int mt = 0; mt < 2; mt++) {
                int r = wm + mt * 16 + g;
                ah[mt][0] = __float_as_uint(Wh[r    ][kk + tig    ]);
                ah[mt][1] = __float_as_uint(Wh[r + 8][kk + tig    ]);
                ah[mt][2] = __float_as_uint(Wh[r    ][kk + tig + 4]);
                ah[mt][3] = __float_as_uint(Wh[r + 8][kk + tig + 4]);
                al[mt][0] = f2tf32(Wl[r    ][kk + tig    ]);
                al[mt][1] = f2tf32(Wl[r + 8][kk + tig    ]);
                al[mt][2] = f2tf32(Wl[r    ][kk + tig + 4]);
                al[mt][3] = f2tf32(Wl[r + 8][kk + tig + 4]);
            }
#pragma unroll
            for (int j = 0; j < 8; j++) {
                int col = wn + j * 8 + g;
                uint32_t bh0 = __float_as_uint(Xh[kk + tig    ][col]);
                uint32_t bh1 = __float_as_uint(Xh[kk + tig + 4][col]);
                uint32_t bl0 = f2tf32(Xl[kk + tig    ][col]);
                uint32_t bl1 = f2tf32(Xl[kk + tig + 4][col]);
#pragma unroll
                for (int mt = 0; mt < 2; mt++) {
                    mma_tf32(acc[mt][j][0], acc[mt][j][1], acc[mt][j][2], acc[mt][j][3],
                             ah[mt][0], ah[mt][1], ah[mt][2], ah[mt][3], bh0, bh1);
                    mma_tf32(acc[mt][j][0], acc[mt][j][1], acc[mt][j][2], acc[mt][j][3],
                             ah[mt][0], ah[mt][1], ah[mt][2], ah[mt][3], bl0, bl1);
                    mma_tf32(acc[mt][j][0], acc[mt][j][1], acc[mt][j][2], acc[mt][j][3],
                             al[mt][0], al[mt][1], al[mt][2], al[mt][3], bh0, bh1);
                }
            }
        }
    }

#pragma unroll
    for (int mt = 0; mt < 2; mt++) {
        int r0 = n0 + wm + mt * 16 + g;
#pragma unroll
        for (int j = 0; j < 8; j++) {
            int t = t0 + wn + j * 8 + 2 * tig;
            int c = t >> 5, h = t & 31;
            float* base = &Out[((size_t)(c * 16 + b) * kN) * kH + h];
            *(float2*)&base[(size_t)r0 * kH]       = make_float2(acc[mt][j][0], acc[mt][j][1]);
            *(float2*)&base[(size_t)(r0 + 8) * kH] = make_float2(acc[mt][j][2], acc[mt][j][3]);
        }
    }
}

// ---------------- K2: scores via tf32 mma; writes g_P TRANSPOSED [m][n] -----------
__global__ void __launch_bounds__(256) scores_kernel(const int* __restrict__ pm) {
    int cb = blockIdx.z;
    int bb = cb & 15;
    int m0 = blockIdx.x * 64, n0 = blockIdx.y * 64;
    const float* Q = g_Q + (size_t)cb * kN * kH;
    const float* K = g_K + (size_t)cb * kN * kH;

    __shared__ float Qh[64][36], Ql[64][36];
    __shared__ float Kh2[64][36], Kl[64][36];
    __shared__ int pmsk[64];

    int tid = threadIdx.x;              // 256
    if (tid < 64) pmsk[tid] = pm[bb * kN + m0 + tid];

#pragma unroll
    for (int i = 0; i < 2; i++) {
        int idx = tid + i * 256;
        int r = idx >> 3, c4 = idx & 7;
        float4 v = *(const float4*)&Q[(size_t)(n0 + r) * kH + c4 * 4];
        float h0,l0,h1,l1,h2,l2,h3,l3;
        split_tf32(v.x, h0, l0); split_tf32(v.y, h1, l1);
        split_tf32(v.z, h2, l2); split_tf32(v.w, h3, l3);
        Qh[r][c4*4+0]=h0; Qh[r][c4*4+1]=h1; Qh[r][c4*4+2]=h2; Qh[r][c4*4+3]=h3;
        Ql[r][c4*4+0]=l0; Ql[r][c4*4+1]=l1; Ql[r][c4*4+2]=l2; Ql[r][c4*4+3]=l3;
        float4 u = *(const float4*)&K[(size_t)(m0 + r) * kH + c4 * 4];
        split_tf32(u.x, h0, l0); split_tf32(u.y, h1, l1);
        split_tf32(u.z, h2, l2); split_tf32(u.w, h3, l3);
        Kh2[r][c4*4+0]=h0; Kh2[r][c4*4+1]=h1; Kh2[r][c4*4+2]=h2; Kh2[r][c4*4+3]=h3;
        Kl[r][c4*4+0]=l0; Kl[r][c4*4+1]=l1; Kl[r][c4*4+2]=l2; Kl[r][c4*4+3]=l3;
    }
    __syncthreads();

    int w = tid >> 5, lane = tid & 31;
    int g = lane >> 2, tig = lane & 3;
    int wm = (w & 1) * 32;              // n offset within 64
    int wnn = (w >> 1) * 16;            // m offset within 64

    float acc[2][2][4] = {};

#pragma unroll
    for (int kk = 0; kk < 32; kk += 8) {
        uint32_t ah[2][4], al[2][4];
#pragma unroll
        for (int mt = 0; mt < 2; mt++) {
            int r = wm + mt * 16 + g;
            ah[mt][0] = __float_as_uint(Qh[r    ][kk + tig    ]);
            ah[mt][1] = __float_as_uint(Qh[r + 8][kk + tig    ]);
            ah[mt][2] = __float_as_uint(Qh[r    ][kk + tig + 4]);
            ah[mt][3] = __float_as_uint(Qh[r + 8][kk + tig + 4]);
            al[mt][0] = f2tf32(Ql[r    ][kk + tig    ]);
            al[mt][1] = f2tf32(Ql[r + 8][kk + tig    ]);
            al[mt][2] = f2tf32(Ql[r    ][kk + tig + 4]);
            al[mt][3] = f2tf32(Ql[r + 8][kk + tig + 4]);
        }
#pragma unroll
        for (int j = 0; j < 2; j++) {
            int col = wnn + j * 8 + g;
            uint32_t bh0 = __float_as_uint(Kh2[col][kk + tig    ]);
            uint32_t bh1 = __float_as_uint(Kh2[col][kk + tig + 4]);
            uint32_t bl0 = f2tf32(Kl[col][kk + tig    ]);
            uint32_t bl1 = f2tf32(Kl[col][kk + tig + 4]);
#pragma unroll
            for (int mt = 0; mt < 2; mt++) {
                mma_tf32(acc[mt][j][0], acc[mt][j][1], acc[mt][j][2], acc[mt][j][3],
                         ah[mt][0], ah[mt][1], ah[mt][2], ah[mt][3], bh0, bh1);
                mma_tf32(acc[mt][j][0], acc[mt][j][1], acc[mt][j][2], acc[mt][j][3],
                         ah[mt][0], ah[mt][1], ah[mt][2], ah[mt][3], bl0, bl1);
                mma_tf32(acc[mt][j][0], acc[mt][j][1], acc[mt][j][2], acc[mt][j][3],
                         al[mt][0], al[mt][1], al[mt][2], al[mt][3], bh0, bh1);
            }
        }
    }

    // epilogue with key mask, TRANSPOSED store g_P[cb][m][n]
    float* Pt = g_P + (size_t)cb * kNN;
#pragma unroll
    for (int mt = 0; mt < 2; mt++) {
        int n = n0 + wm + mt * 16 + g;
#pragma unroll
        for (int j = 0; j < 2; j++) {
            int mc = wnn + j * 8 + 2 * tig;
            int m = m0 + mc;
            float c0 = (pmsk[mc]     == 0) ? kNEG : acc[mt][j][0];
            float c1 = (pmsk[mc + 1] == 0) ? kNEG : acc[mt][j][1];
            float c2 = (pmsk[mc]     == 0) ? kNEG : acc[mt][j][2];
            float c3 = (pmsk[mc + 1] == 0) ? kNEG : acc[mt][j][3];
            Pt[(size_t)m * kN + n]           = c0;
            Pt[(size_t)(m + 1) * kN + n]     = c1;
            Pt[(size_t)m * kN + n + 8]       = c2;
            Pt[(size_t)(m + 1) * kN + n + 8] = c3;
        }
    }
}

// ---------------- K3: online max & sumexp over axis 0; d = mx + ln(0.9 s) ---------
// UNCHANGED — serves as the environment/clock normalizer across rounds.
__global__ void __launch_bounds__(256) maxsum_kernel() {
    int idx = blockIdx.x * blockDim.x + threadIdx.x;  // 0..N*N-1 (= m*kN + n)
    const float* p = g_P + idx;
    float mx = __int_as_float(0xff800000);            // -inf
    float s = 0.0f;
    for (int cb = 0; cb < kCB; cb += 8) {
        float v[8];
#pragma unroll
        for (int u = 0; u < 8; u++) v[u] = p[(size_t)(cb + u) * kNN];
#pragma unroll
        for (int u = 0; u < 8; u++) {
            float vv = v[u];
            if (vv > mx) { s = s * __expf(mx - vv) + 1.0f; mx = vv; }
            else         { s += __expf(vv - mx); }
        }
    }
    g_d[idx] = mx + __logf(kKEEP * s);
}

// ---------------- K4: ctx = dropout(softmax) @ Vh, tf32 mma -----------------------
// P single tf32 plane. Fill phase restructured: load pass (MLP 8) then compute
// pass (8 independent threefry chains unrolled together for ILP).
__global__ void __launch_bounds__(256) ctx_kernel(float* __restrict__ out) {
    int cb = blockIdx.y;
    int n0 = blockIdx.x * 64;
    int bb = cb & 15;
    const float* Pt = g_P + (size_t)cb * kNN;   // [m][n]
    const float* V = g_V + (size_t)cb * kN * kH;

    __shared__ float Ph[32][72];                // [m][n]  (m-tile 32), tf32 values
    __shared__ float Vth[32][36], Vtl[32][36];  // [h][m]
    __shared__ int skipw[kN];

    int tid = threadIdx.x;                      // 256
    for (int i = tid; i < kN; i += 256) skipw[i] = g_skip[bb * kN + i];

    int w = tid >> 5, l = tid & 31;
    int g = l >> 2, tig = l & 3;
    int wh = (w & 1) * 16;                      // h-offset of warp tile (A rows)
    int wn = (w >> 1) * 16;                     // n-offset of warp tile (B cols)

    float acc[2][4] = {};                       // [j][frag]: D[h][n], 16h x 16n/warp

    __syncthreads();

    for (int m0 = 0; m0 < kN; m0 += 32) {
        // ---- V tile transpose: [m][h] -> [h][m], split hi/lo ----
        {
            int k = tid >> 3, h4 = tid & 7;
            float4 v = *(const float4*)&V[(size_t)(m0 + k) * kH + h4 * 4];
            float h0,l0,h1,l1,h2,l2,h3,l3;
            split_tf32(v.x, h0, l0); split_tf32(v.y, h1, l1);
            split_tf32(v.z, h2, l2); split_tf32(v.w, h3, l3);
            Vth[h4*4+0][k]=h0; Vth[h4*4+1][k]=h1; Vth[h4*4+2][k]=h2; Vth[h4*4+3][k]=h3;
            Vtl[h4*4+0][k]=l0; Vtl[h4*4+1][k]=l1; Vtl[h4*4+2][k]=l2; Vtl[h4*4+3][k]=l3;
        }
        // ---- fill pass 1: conditional loads, batched for MLP ----
        float pv[4][2], dv[4][2];
        int skv[4];
#pragma unroll
        for (int j = 0; j < 4; j++) {
            int m = m0 + w * 4 + j;
            int sk = skipw[m];
            skv[j] = sk;
            if (sk == 0) {
                const float* prow = &Pt[(size_t)m * kN + n0];
                const float* drow = &g_d[m * kN + n0];
                pv[j][0] = prow[l];      pv[j][1] = prow[l + 32];
                dv[j][0] = drow[l];      dv[j][1] = drow[l + 32];
            }
        }
        // ---- fill pass 2: threefry + exp + store (8 independent chains) ----
#pragma unroll
        for (int j = 0; j < 4; j++) {
            int ml = w * 4 + j;
            int m = m0 + ml;
            int sk = skv[j];
            if (sk == 1) {
                Ph[ml][l] = 0.0f; Ph[ml][l + 32] = 0.0f;
            } else {
#pragma unroll
                for (int rr = 0; rr < 2; rr++) {
                    int nl = l + rr * 32;
                    float pr = (sk == 2) ? kUnif
                                         : __expf(pv[j][rr] - dv[j][rr]);
                    uint32_t gi = (uint32_t)(((size_t)cb * kN + n0 + nl) * kN + m);
                    uint32_t bits = rng_bits(1u, gi);   // key(1), LOGICAL index
                    float val = keep_bit(bits) ? pr : 0.0f;
                    Ph[ml][nl] = __uint_as_float(f2tf32(val));
                }
            }
        }
        __syncthreads();
        // ---- MMA: A = Vt (16 h rows, hi+lo), B = P (tf32), k = 32 m ----
#pragma unroll
        for (int kk = 0; kk < 32; kk += 8) {
            int r = wh + g;
            uint32_t ah[4], al[4];
            ah[0] = __float_as_uint(Vth[r    ][kk + tig    ]);
            ah[1] = __float_as_uint(Vth[r + 8][kk + tig    ]);
            ah[2] = __float_as_uint(Vth[r    ][kk + tig + 4]);
            ah[3] = __float_as_uint(Vth[r + 8][kk + tig + 4]);
            al[0] = f2tf32(Vtl[r    ][kk + tig    ]);
            al[1] = f2tf32(Vtl[r + 8][kk + tig    ]);
            al[2] = f2tf32(Vtl[r    ][kk + tig + 4]);
            al[3] = f2tf32(Vtl[r + 8][kk + tig + 4]);
#pragma unroll
            for (int j = 0; j < 2; j++) {
                int col = wn + j * 8 + g;
                uint32_t bh0 = __float_as_uint(Ph[kk + tig    ][col]);
                uint32_t bh1 = __float_as_uint(Ph[kk + tig + 4][col]);
                mma_tf32(acc[j][0], acc[j][1], acc[j][2], acc[j][3],
                         ah[0], ah[1], ah[2], ah[3], bh0, bh1);
                mma_tf32(acc[j][0], acc[j][1], acc[j][2], acc[j][3],
                         al[0], al[1], al[2], al[3], bh0, bh1);
            }
        }
        __syncthreads();
    }

    // epilogue: D[h][n] -> out[jj, n, ii*32+h] with cb = ii*32+jj; dropout key(2)
    int jpart = (cb & 31) * (kN * kB * kH) + (cb >> 5) * kH;
#pragma unroll
    for (int j = 0; j < 2; j++) {
        int nc = n0 + wn + j * 8 + 2 * tig;
#pragma unroll
        for (int rr = 0; rr < 2; rr++) {
            int h = wh + g + rr * 8;
            int oidx0 = jpart + nc * (kB * kH) + h;
            int oidx1 = oidx0 + kB * kH;        // n+1
            float v0 = acc[j][rr * 2 + 0];
            float v1 = acc[j][rr * 2 + 1];
            uint32_t b0 = rng_bits(2u, (uint32_t)oidx0);
            uint32_t b1 = rng_bits(2u, (uint32_t)oidx1);
            out[oidx0] = keep_bit(b0) ? v0 * kRKEEP : 0.0f;
            out[oidx1] = keep_bit(b1) ? v1 * kRKEEP : 0.0f;
        }
    }
}

// ---------------- K5: attention = dropout(probs)[:, N-1, :] recomputed ------------
__global__ void __launch_bounds__(256) attn_kernel(float* __restrict__ out) {
    int idx = blockIdx.x * blockDim.x + threadIdx.x;  // 0..kATTSZ-1
    int cb = idx >> 9, m = idx & 511;
    int bb = cb & 15;
    int sk = g_skip[bb * kN + m];
    size_t ti = (size_t)cb * kNN + (size_t)m * kN + (kN - 1);
    float pr = (sk == 2) ? kUnif : __expf(g_P[ti] - g_d[m * kN + (kN - 1)]);
    uint32_t gi = (uint32_t)(((size_t)cb * kN + (kN - 1)) * kN + m);  // logical
    uint32_t bits = rng_bits(1u, gi);
    out[kOUTSZ + idx] = keep_bit(bits) ? pr : 0.0f;
}

extern "C" void kernel_launch(void* const* d_in, const int* in_sizes, int n_in,
                              void* d_out, int out_size) {
    const float* x  = (const float*)d_in[0];
    const float* Qp = (const float*)d_in[1];
    const float* Kp = (const float*)d_in[2];
    const float* Vp = (const float*)d_in[3];
    const int*   pm = (const int*)d_in[4];
    float* out = (float*)d_out;

    skip_kernel  <<<(kB * kN) / 256, 256>>>(pm);
    proj_kernel  <<<dim3(kT / 128, kN / 128, 48), 256>>>(x, Qp, Kp, Vp);
    scores_kernel<<<dim3(kN / 64, kN / 64, kCB), 256>>>(pm);
    maxsum_kernel<<<kNN / 256, 256>>>();
    ctx_kernel   <<<dim3(kN / 64, kCB), 256>>>(out);
    if (out_size >= kOUTSZ + kATTSZ) {
        attn_kernel<<<kATTSZ / 256, 256>>>(out);
    }
}

// round 17
// speedup vs baseline: 1.5192x; 1.0819x over previous
#include <cuda_runtime.h>
#include <cstdint>
#include <cstddef>

// Problem dims
constexpr int kB  = 16;    // batch
constexpr int kN  = 512;   // num inputs
constexpr int kU  = 512;   // num units
constexpr int kT  = 1024;  // time = H*H
constexpr int kH  = 32;    // heads
constexpr int kCB = 512;   // C*B
constexpr float kNEG  = -4294967296.0f;  // float32(-2^32+1)
constexpr float kKEEP = 0.9f;
constexpr float kRKEEP = 1.0f / 0.9f;
constexpr float kUnif  = 1.0f / (0.9f * 512.0f);  // uniform prob for all-masked col

constexpr int    kNN     = kN * kN;                 // 262144
constexpr size_t kPSZ    = (size_t)kCB * kNN;       // 134217728
constexpr int    kOUTSZ  = kH * kN * kB * kH;       // 8388608
constexpr int    kATTSZ  = kCB * kN;                // 262144

// Scratch (__device__ globals per allocation-free contract)
// NOTE: g_P and g_d are stored TRANSPOSED: linear index = m*kN + n (per cb).
// Threefry indices always use the LOGICAL index ((cb*N + n)*N + m).
__device__ float g_Q[(size_t)kCB * kN * kH];
__device__ float g_K[(size_t)kCB * kN * kH];
__device__ float g_V[(size_t)kCB * kN * kH];
__device__ float g_P[kPSZ];          // raw (masked) scores, [cb][m][n]
__device__ float g_d[kNN];           // mx + ln(0.9 * sum_exp), [m][n]
__device__ int   g_skip[kB * kN];    // 0 normal / 1 zero-col / 2 uniform-col

// ---------------- threefry2x32 (exact JAX PRNG, partitionable layout) --------------
__device__ __forceinline__ void tf_round(uint32_t& a, uint32_t& b, int r) {
    a += b;
    b = __funnelshift_l(b, b, r);
    b ^= a;
}
__device__ __forceinline__ void threefry(uint32_t k0, uint32_t k1,
                                         uint32_t& x0, uint32_t& x1) {
    uint32_t k2 = k0 ^ k1 ^ 0x1BD11BDAu;
    x0 += k0; x1 += k1;
    tf_round(x0,x1,13); tf_round(x0,x1,15); tf_round(x0,x1,26); tf_round(x0,x1,6);
    x0 += k1; x1 += k2 + 1u;
    tf_round(x0,x1,17); tf_round(x0,x1,29); tf_round(x0,x1,16); tf_round(x0,x1,24);
    x0 += k2; x1 += k0 + 2u;
    tf_round(x0,x1,13); tf_round(x0,x1,15); tf_round(x0,x1,26); tf_round(x0,x1,6);
    x0 += k0; x1 += k1 + 3u;
    tf_round(x0,x1,17); tf_round(x0,x1,29); tf_round(x0,x1,16); tf_round(x0,x1,24);
    x0 += k1; x1 += k2 + 4u;
    tf_round(x0,x1,13); tf_round(x0,x1,15); tf_round(x0,x1,26); tf_round(x0,x1,6);
    x0 += k2; x1 += k0 + 5u;
}
__device__ __forceinline__ uint32_t rng_bits(uint32_t k1, uint32_t idx) {
    uint32_t x0 = 0u, x1 = idx;
    threefry(0u, k1, x0, x1);
    return x0 ^ x1;
}
// keep iff uniform(bits) < 0.9f.  u = (bits>>9)*2^-23 exactly; 0.9f = 7549747*2^-23
// exactly, so the float compare is equivalent to this integer compare (bit-exact).
__device__ __forceinline__ bool keep_bit(uint32_t bits) {
    return (bits >> 9) < 7549747u;
}

// ---------------- tf32 helpers ----------------
__device__ __forceinline__ uint32_t f2tf32(float v) {
    uint32_t r;
    asm("cvt.rna.tf32.f32 %0, %1;" : "=r"(r) : "f"(v));
    return r;
}
__device__ __forceinline__ void split_tf32(float v, float& hi, float& lo) {
    uint32_t h = f2tf32(v);
    hi = __uint_as_float(h);
    lo = v - hi;
}
__device__ __forceinline__ void mma_tf32(float& d0, float& d1, float& d2, float& d3,
                                         uint32_t a0, uint32_t a1, uint32_t a2, uint32_t a3,
                                         uint32_t b0, uint32_t b1) {
    asm volatile(
        "mma.sync.aligned.m16n8k8.row.col.f32.tf32.tf32.f32 "
        "{%0,%1,%2,%3}, {%4,%5,%6,%7}, {%8,%9}, {%0,%1,%2,%3};"
        : "+f"(d0), "+f"(d1), "+f"(d2), "+f"(d3)
        : "r"(a0), "r"(a1), "r"(a2), "r"(a3), "r"(b0), "r"(b1));
}

// ---------------- K0: per-(b,m) skip codes from padding mask ----------------------
__global__ void __launch_bounds__(256) skip_kernel(const int* __restrict__ pm) {
    int idx = blockIdx.x * blockDim.x + threadIdx.x;   // 0..kB*kN-1
    int b = idx >> 9, m = idx & 511;
    bool allm = true;
#pragma unroll
    for (int bb = 0; bb < kB; bb++) allm = allm && (pm[bb * kN + m] == 0);
    int code = 0;
    if (allm) code = 2;                                // uniform softmax column
    else if (pm[b * kN + m] == 0) code = 1;            // exactly-zero column
    g_skip[idx] = code;
}

// ---------------- K1: projections via tf32 mma, register-prefetch double buffer ---
__global__ void __launch_bounds__(256) proj_kernel(const float* __restrict__ x,
                                                   const float* __restrict__ Qp,
                                                   const float* __restrict__ Kp,
                                                   const float* __restrict__ Vp) {
    int z = blockIdx.z;                 // mat*16 + b
    int mat = z >> 4, b = z & 15;
    const float* W  = (mat == 0) ? Qp : ((mat == 1) ? Kp : Vp);
    float* Out      = (mat == 0) ? g_Q : ((mat == 1) ? g_K : g_V);
    const float* X  = x + (size_t)b * kU * kT;

    int n0 = blockIdx.y * 128;          // output n (m-dim)
    int t0 = blockIdx.x * 128;          // output t (n-dim)

    __shared__ float Wh[128][20];
    __shared__ float Wl[128][20];
    __shared__ float Xh[16][136];
    __shared__ float Xl[16][136];

    int tid = threadIdx.x;              // 256
    int w   = tid >> 5;
    int lane= tid & 31;
    int g   = lane >> 2;
    int tig = lane & 3;

    int wm = (w & 3) * 32;
    int wn = (w >> 2) * 64;

    // loader indices (2 float4 per tile per thread)
    int wn_r[2], wc4[2], xk[2], xc4[2];
#pragma unroll
    for (int i = 0; i < 2; i++) {
        int idx = tid + i * 256;
        wn_r[i] = idx >> 2; wc4[i] = idx & 3;
        xk[i]   = idx >> 5; xc4[i] = idx & 31;
    }

    float acc[2][8][4] = {};

    // prefetch first tiles into registers
    float4 wreg[2], xreg[2];
#pragma unroll
    for (int i = 0; i < 2; i++) {
        wreg[i] = *(const float4*)&W[(size_t)(n0 + wn_r[i]) * kU + wc4[i] * 4];
        xreg[i] = *(const float4*)&X[(size_t)xk[i] * kT + t0 + xc4[i] * 4];
    }

    for (int k0 = 0; k0 < kU; k0 += 16) {
        __syncthreads();
        // split + store the prefetched registers
#pragma unroll
        for (int i = 0; i < 2; i++) {
            int n = wn_r[i], c4 = wc4[i];
            float h0,l0,h1,l1,h2,l2,h3,l3;
            split_tf32(wreg[i].x, h0, l0); split_tf32(wreg[i].y, h1, l1);
            split_tf32(wreg[i].z, h2, l2); split_tf32(wreg[i].w, h3, l3);
            Wh[n][c4*4+0] = h0; Wh[n][c4*4+1] = h1; Wh[n][c4*4+2] = h2; Wh[n][c4*4+3] = h3;
            Wl[n][c4*4+0] = l0; Wl[n][c4*4+1] = l1; Wl[n][c4*4+2] = l2; Wl[n][c4*4+3] = l3;
            int k = xk[i], xc = xc4[i];
            split_tf32(xreg[i].x, h0, l0); split_tf32(xreg[i].y, h1, l1);
            split_tf32(xreg[i].z, h2, l2); split_tf32(xreg[i].w, h3, l3);
            Xh[k][xc*4+0] = h0; Xh[k][xc*4+1] = h1; Xh[k][xc*4+2] = h2; Xh[k][xc*4+3] = h3;
            Xl[k][xc*4+0] = l0; Xl[k][xc*4+1] = l1; Xl[k][xc*4+2] = l2; Xl[k][xc*4+3] = l3;
        }
        __syncthreads();
        // issue next tile's loads BEFORE the MMA phase (latency hidden by MMAs)
        if (k0 + 16 < kU) {
#pragma unroll
            for (int i = 0; i < 2; i++) {
                wreg[i] = *(const float4*)&W[(size_t)(n0 + wn_r[i]) * kU + k0 + 16 + wc4[i] * 4];
                xreg[i] = *(const float4*)&X[(size_t)(k0 + 16 + xk[i]) * kT + t0 + xc4[i] * 4];
            }
        }

#pragma unroll
        for (int kk = 0; kk < 16; kk += 8) {
            uint32_t ah[2][4], al[2][4];
#pragma unroll
            for (int mt = 0; mt < 2; mt++) {
                int r = wm + mt * 16 + g;
                ah[mt][0] = __float_as_uint(Wh[r    ][kk + tig    ]);
                ah[mt][1] = __float_as_uint(Wh[r + 8][kk + tig    ]);
                ah[mt][2] = __float_as_uint(Wh[r    ][kk + tig + 4]);
                ah[mt][3] = __float_as_uint(Wh[r + 8][kk + tig + 4]);
                al[mt][0] = f2tf32(Wl[r    ][kk + tig    ]);
                al[mt][1] = f2tf32(Wl[r + 8][kk + tig    ]);
                al[mt][2] = f2tf32(Wl[r    ][kk + tig + 4]);
                al[mt][3] = f2tf32(Wl[r + 8][kk + tig + 4]);
            }
#pragma unroll
            for (int j = 0; j < 8; j++) {
                int col = wn + j * 8 + g;
                uint32_t bh0 = __float_as_uint(Xh[kk + tig    ][col]);
                uint32_t bh1 = __float_as_uint(Xh[kk + tig + 4][col]);
                uint32_t bl0 = f2tf32(Xl[kk + tig    ][col]);
                uint32_t bl1 = f2tf32(Xl[kk + tig + 4][col]);
#pragma unroll
                for (int mt = 0; mt < 2; mt++) {
                    mma_tf32(acc[mt][j][0], acc[mt][j][1], acc[mt][j][2], acc[mt][j][3],
                             ah[mt][0], ah[mt][1], ah[mt][2], ah[mt][3], bh0, bh1);
                    mma_tf32(acc[mt][j][0], acc[mt][j][1], acc[mt][j][2], acc[mt][j][3],
                             ah[mt][0], ah[mt][1], ah[mt][2], ah[mt][3], bl0, bl1);
                    mma_tf32(acc[mt][j][0], acc[mt][j][1], acc[mt][j][2], acc[mt][j][3],
                             al[mt][0], al[mt][1], al[mt][2], al[mt][3], bh0, bh1);
                }
            }
        }
    }

#pragma unroll
    for (int mt = 0; mt < 2; mt++) {
        int r0 = n0 + wm + mt * 16 + g;
#pragma unroll
        for (int j = 0; j < 8; j++) {
            int t = t0 + wn + j * 8 + 2 * tig;
            int c = t >> 5, h = t & 31;
            float* base = &Out[((size_t)(c * 16 + b) * kN) * kH + h];
            *(float2*)&base[(size_t)r0 * kH]       = make_float2(acc[mt][j][0], acc[mt][j][1]);
            *(float2*)&base[(size_t)(r0 + 8) * kH] = make_float2(acc[mt][j][2], acc[mt][j][3]);
        }
    }
}

// ---------------- K2: scores via tf32 mma; writes g_P TRANSPOSED [m][n] -----------
__global__ void __launch_bounds__(256) scores_kernel(const int* __restrict__ pm) {
    int cb = blockIdx.z;
    int bb = cb & 15;
    int m0 = blockIdx.x * 64, n0 = blockIdx.y * 64;
    const float* Q = g_Q + (size_t)cb * kN * kH;
    const float* K = g_K + (size_t)cb * kN * kH;

    __shared__ float Qh[64][36], Ql[64][36];
    __shared__ float Kh2[64][36], Kl[64][36];
    __shared__ int pmsk[64];

    int tid = threadIdx.x;              // 256
    if (tid < 64) pmsk[tid] = pm[bb * kN + m0 + tid];

#pragma unroll
    for (int i = 0; i < 2; i++) {
        int idx = tid + i * 256;
        int r = idx >> 3, c4 = idx & 7;
        float4 v = *(const float4*)&Q[(size_t)(n0 + r) * kH + c4 * 4];
        float h0,l0,h1,l1,h2,l2,h3,l3;
        split_tf32(v.x, h0, l0); split_tf32(v.y, h1, l1);
        split_tf32(v.z, h2, l2); split_tf32(v.w, h3, l3);
        Qh[r][c4*4+0]=h0; Qh[r][c4*4+1]=h1; Qh[r][c4*4+2]=h2; Qh[r][c4*4+3]=h3;
        Ql[r][c4*4+0]=l0; Ql[r][c4*4+1]=l1; Ql[r][c4*4+2]=l2; Ql[r][c4*4+3]=l3;
        float4 u = *(const float4*)&K[(size_t)(m0 + r) * kH + c4 * 4];
        split_tf32(u.x, h0, l0); split_tf32(u.y, h1, l1);
        split_tf32(u.z, h2, l2); split_tf32(u.w, h3, l3);
        Kh2[r][c4*4+0]=h0; Kh2[r][c4*4+1]=h1; Kh2[r][c4*4+2]=h2; Kh2[r][c4*4+3]=h3;
        Kl[r][c4*4+0]=l0; Kl[r][c4*4+1]=l1; Kl[r][c4*4+2]=l2; Kl[r][c4*4+3]=l3;
    }
    __syncthreads();

    int w = tid >> 5, lane = tid & 31;
    int g = lane >> 2, tig = lane & 3;
    int wm = (w & 1) * 32;              // n offset within 64
    int wnn = (w >> 1) * 16;            // m offset within 64

    float acc[2][2][4] = {};

#pragma unroll
    for (int kk = 0; kk < 32; kk += 8) {
        uint32_t ah[2][4], al[2][4];
#pragma unroll
        for (int mt = 0; mt < 2; mt++) {
            int r = wm + mt * 16 + g;
            ah[mt][0] = __float_as_uint(Qh[r    ][kk + tig    ]);
            ah[mt][1] = __float_as_uint(Qh[r + 8][kk + tig    ]);
            ah[mt][2] = __float_as_uint(Qh[r    ][kk + tig + 4]);
            ah[mt][3] = __float_as_uint(Qh[r + 8][kk + tig + 4]);
            al[mt][0] = f2tf32(Ql[r    ][kk + tig    ]);
            al[mt][1] = f2tf32(Ql[r + 8][kk + tig    ]);
            al[mt][2] = f2tf32(Ql[r    ][kk + tig + 4]);
            al[mt][3] = f2tf32(Ql[r + 8][kk + tig + 4]);
        }
#pragma unroll
        for (int j = 0; j < 2; j++) {
            int col = wnn + j * 8 + g;
            uint32_t bh0 = __float_as_uint(Kh2[col][kk + tig    ]);
            uint32_t bh1 = __float_as_uint(Kh2[col][kk + tig + 4]);
            uint32_t bl0 = f2tf32(Kl[col][kk + tig    ]);
            uint32_t bl1 = f2tf32(Kl[col][kk + tig + 4]);
#pragma unroll
            for (int mt = 0; mt < 2; mt++) {
                mma_tf32(acc[mt][j][0], acc[mt][j][1], acc[mt][j][2], acc[mt][j][3],
                         ah[mt][0], ah[mt][1], ah[mt][2], ah[mt][3], bh0, bh1);
                mma_tf32(acc[mt][j][0], acc[mt][j][1], acc[mt][j][2], acc[mt][j][3],
                         ah[mt][0], ah[mt][1], ah[mt][2], ah[mt][3], bl0, bl1);
                mma_tf32(acc[mt][j][0], acc[mt][j][1], acc[mt][j][2], acc[mt][j][3],
                         al[mt][0], al[mt][1], al[mt][2], al[mt][3], bh0, bh1);
            }
        }
    }

    // epilogue with key mask, TRANSPOSED store g_P[cb][m][n]
    float* Pt = g_P + (size_t)cb * kNN;
#pragma unroll
    for (int mt = 0; mt < 2; mt++) {
        int n = n0 + wm + mt * 16 + g;
#pragma unroll
        for (int j = 0; j < 2; j++) {
            int mc = wnn + j * 8 + 2 * tig;
            int m = m0 + mc;
            float c0 = (pmsk[mc]     == 0) ? kNEG : acc[mt][j][0];
            float c1 = (pmsk[mc + 1] == 0) ? kNEG : acc[mt][j][1];
            float c2 = (pmsk[mc]     == 0) ? kNEG : acc[mt][j][2];
            float c3 = (pmsk[mc + 1] == 0) ? kNEG : acc[mt][j][3];
            Pt[(size_t)m * kN + n]           = c0;
            Pt[(size_t)(m + 1) * kN + n]     = c1;
            Pt[(size_t)m * kN + n + 8]       = c2;
            Pt[(size_t)(m + 1) * kN + n + 8] = c3;
        }
    }
}

// ---------------- K3: online max & sumexp over axis 0; d = mx + ln(0.9 s) ---------
// UNCHANGED — serves as the environment/clock normalizer across rounds.
__global__ void __launch_bounds__(256) maxsum_kernel() {
    int idx = blockIdx.x * blockDim.x + threadIdx.x;  // 0..N*N-1 (= m*kN + n)
    const float* p = g_P + idx;
    float mx = __int_as_float(0xff800000);            // -inf
    float s = 0.0f;
    for (int cb = 0; cb < kCB; cb += 8) {
        float v[8];
#pragma unroll
        for (int u = 0; u < 8; u++) v[u] = p[(size_t)(cb + u) * kNN];
#pragma unroll
        for (int u = 0; u < 8; u++) {
            float vv = v[u];
            if (vv > mx) { s = s * __expf(mx - vv) + 1.0f; mx = vv; }
            else         { s += __expf(vv - mx); }
        }
    }
    g_d[idx] = mx + __logf(kKEEP * s);
}

// ---------------- K4: ctx = dropout(softmax) @ Vh, tf32 mma -----------------------
// P single tf32 plane. Fill: load pass (MLP) then compute pass (ILP threefry).
__global__ void __launch_bounds__(256) ctx_kernel(float* __restrict__ out) {
    int cb = blockIdx.y;
    int n0 = blockIdx.x * 64;
    int bb = cb & 15;
    const float* Pt = g_P + (size_t)cb * kNN;   // [m][n]
    const float* V = g_V + (size_t)cb * kN * kH;

    __shared__ float Ph[32][72];                // [m][n]  (m-tile 32), tf32 values
    __shared__ float Vth[32][36], Vtl[32][36];  // [h][m]
    __shared__ int skipw[kN];

    int tid = threadIdx.x;                      // 256
    for (int i = tid; i < kN; i += 256) skipw[i] = g_skip[bb * kN + i];

    int w = tid >> 5, l = tid & 31;
    int g = l >> 2, tig = l & 3;
    int wh = (w & 1) * 16;                      // h-offset of warp tile (A rows)
    int wn = (w >> 1) * 16;                     // n-offset of warp tile (B cols)

    float acc[2][4] = {};                       // [j][frag]: D[h][n], 16h x 16n/warp

    __syncthreads();

    for (int m0 = 0; m0 < kN; m0 += 32) {
        // ---- V tile transpose: [m][h] -> [h][m], split hi/lo ----
        {
            int k = tid >> 3, h4 = tid & 7;
            float4 v = *(const float4*)&V[(size_t)(m0 + k) * kH + h4 * 4];
            float h0,l0,h1,l1,h2,l2,h3,l3;
            split_tf32(v.x, h0, l0); split_tf32(v.y, h1, l1);
            split_tf32(v.z, h2, l2); split_tf32(v.w, h3, l3);
            Vth[h4*4+0][k]=h0; Vth[h4*4+1][k]=h1; Vth[h4*4+2][k]=h2; Vth[h4*4+3][k]=h3;
            Vtl[h4*4+0][k]=l0; Vtl[h4*4+1][k]=l1; Vtl[h4*4+2][k]=l2; Vtl[h4*4+3][k]=l3;
        }
        // ---- fill pass 1: conditional loads, batched for MLP ----
        float pv[4][2], dv[4][2];
        int skv[4];
#pragma unroll
        for (int j = 0; j < 4; j++) {
            int m = m0 + w * 4 + j;
            int sk = skipw[m];
            skv[j] = sk;
            if (sk == 0) {
                const float* prow = &Pt[(size_t)m * kN + n0];
                const float* drow = &g_d[m * kN + n0];
                pv[j][0] = prow[l];      pv[j][1] = prow[l + 32];
                dv[j][0] = drow[l];      dv[j][1] = drow[l + 32];
            }
        }
        // ---- fill pass 2: threefry + exp + store (8 independent chains) ----
#pragma unroll
        for (int j = 0; j < 4; j++) {
            int ml = w * 4 + j;
            int m = m0 + ml;
            int sk = skv[j];
            if (sk == 1) {
                Ph[ml][l] = 0.0f; Ph[ml][l + 32] = 0.0f;
            } else {
#pragma unroll
                for (int rr = 0; rr < 2; rr++) {
                    int nl = l + rr * 32;
                    float pr = (sk == 2) ? kUnif
                                         : __expf(pv[j][rr] - dv[j][rr]);
                    uint32_t gi = (uint32_t)(((size_t)cb * kN + n0 + nl) * kN + m);
                    uint32_t bits = rng_bits(1u, gi);   // key(1), LOGICAL index
                    float val = keep_bit(bits) ? pr : 0.0f;
                    Ph[ml][nl] = __uint_as_float(f2tf32(val));
                }
            }
        }
        __syncthreads();
        // ---- MMA: A = Vt (16 h rows, hi+lo), B = P (tf32), k = 32 m ----
#pragma unroll
        for (int kk = 0; kk < 32; kk += 8) {
            int r = wh + g;
            uint32_t ah[4], al[4];
            ah[0] = __float_as_uint(Vth[r    ][kk + tig    ]);
            ah[1] = __float_as_uint(Vth[r + 8][kk + tig    ]);
            ah[2] = __float_as_uint(Vth[r    ][kk + tig + 4]);
            ah[3] = __float_as_uint(Vth[r + 8][kk + tig + 4]);
            al[0] = f2tf32(Vtl[r    ][kk + tig    ]);
            al[1] = f2tf32(Vtl[r + 8][kk + tig    ]);
            al[2] = f2tf32(Vtl[r    ][kk + tig + 4]);
            al[3] = f2tf32(Vtl[r + 8][kk + tig + 4]);
#pragma unroll
            for (int j = 0; j < 2; j++) {
                int col = wn + j * 8 + g;
                uint32_t bh0 = __float_as_uint(Ph[kk + tig    ][col]);
                uint32_t bh1 = __float_as_uint(Ph[kk + tig + 4][col]);
                mma_tf32(acc[j][0], acc[j][1], acc[j][2], acc[j][3],
                         ah[0], ah[1], ah[2], ah[3], bh0, bh1);
                mma_tf32(acc[j][0], acc[j][1], acc[j][2], acc[j][3],
                         al[0], al[1], al[2], al[3], bh0, bh1);
            }
        }
        __syncthreads();
    }

    // epilogue: D[h][n] -> out[jj, n, ii*32+h] with cb = ii*32+jj; dropout key(2)
    int jpart = (cb & 31) * (kN * kB * kH) + (cb >> 5) * kH;
#pragma unroll
    for (int j = 0; j < 2; j++) {
        int nc = n0 + wn + j * 8 + 2 * tig;
#pragma unroll
        for (int rr = 0; rr < 2; rr++) {
            int h = wh + g + rr * 8;
            int oidx0 = jpart + nc * (kB * kH) + h;
            int oidx1 = oidx0 + kB * kH;        // n+1
            float v0 = acc[j][rr * 2 + 0];
            float v1 = acc[j][rr * 2 + 1];
            uint32_t b0 = rng_bits(2u, (uint32_t)oidx0);
            uint32_t b1 = rng_bits(2u, (uint32_t)oidx1);
            out[oidx0] = keep_bit(b0) ? v0 * kRKEEP : 0.0f;
            out[oidx1] = keep_bit(b1) ? v1 * kRKEEP : 0.0f;
        }
    }
}

// ---------------- K5: attention = dropout(probs)[:, N-1, :] recomputed ------------
__global__ void __launch_bounds__(256) attn_kernel(float* __restrict__ out) {
    int idx = blockIdx.x * blockDim.x + threadIdx.x;  // 0..kATTSZ-1
    int cb = idx >> 9, m = idx & 511;
    int bb = cb & 15;
    int sk = g_skip[bb * kN + m];
    size_t ti = (size_t)cb * kNN + (size_t)m * kN + (kN - 1);
    float pr = (sk == 2) ? kUnif : __expf(g_P[ti] - g_d[m * kN + (kN - 1)]);
    uint32_t gi = (uint32_t)(((size_t)cb * kN + (kN - 1)) * kN + m);  // logical
    uint32_t bits = rng_bits(1u, gi);
    out[kOUTSZ + idx] = keep_bit(bits) ? pr : 0.0f;
}

extern "C" void kernel_launch(void* const* d_in, const int* in_sizes, int n_in,
                              void* d_out, int out_size) {
    const float* x  = (const float*)d_in[0];
    const float* Qp = (const float*)d_in[1];
    const float* Kp = (const float*)d_in[2];
    const float* Vp = (const float*)d_in[3];
    const int*   pm = (const int*)d_in[4];
    float* out = (float*)d_out;

    skip_kernel  <<<(kB * kN) / 256, 256>>>(pm);
    proj_kernel  <<<dim3(kT / 128, kN / 128, 48), 256>>>(x, Qp, Kp, Vp);
    scores_kernel<<<dim3(kN / 64, kN / 64, kCB), 256>>>(pm);
    maxsum_kernel<<<kNN / 256, 256>>>();
    ctx_kernel   <<<dim3(kN / 64, kCB), 256>>>(out);
    if (out_size >= kOUTSZ + kATTSZ) {
        attn_kernel<<<kATTSZ / 256, 256>>>(out);
    }
}